// round 6
// baseline (speedup 1.0000x reference)
#include <cuda_runtime.h>
#include <cuda_bf16.h>
#include <math.h>
#include <cstdint>

#define BB 512
#define ZI 16
#define TT 8
#define DD 128
#define MROWS (BB*ZI)   /* 8192 */
#define NCOLS (BB*TT)   /* 4096 */

#define NSTRIP 8                 /* m-strips; each strip = 8 m-tiles of 128 */
#define NBLK   (NCOLS/128)       /* 32 n-blocks  */
#define NCTA   (NBLK*NSTRIP)     /* 256 CTAs     */

// ---------------- scratch (static __device__, allocation-free) -------------
__device__ __nv_bfloat162 g_imgh [(size_t)MROWS * (DD/2)];   // 2 MB
__device__ __nv_bfloat162 g_texth[(size_t)NCOLS * (DD/2)];   // 1 MB
__device__ float g_diag[NCOLS];
__device__ float g_rowpart[NBLK * BB];          // per n-block row sums
__device__ float g_colpart[NSTRIP * NCOLS];     // per strip col sums
__device__ float g_logden[NCOLS];
__device__ float g_logrow[BB];
__device__ unsigned g_cnt;                      // zero-init, self-resetting

__device__ __forceinline__ uint32_t smem_u32(const void* p) {
    uint32_t a;
    asm("{ .reg .u64 t; cvta.to.shared.u64 t, %1; cvt.u32.u64 %0, t; }"
        : "=r"(a) : "l"(p));
    return a;
}

#define CPASYNC16(dst,src) \
    asm volatile("cp.async.ca.shared.global [%0], [%1], 16;" \
                 :: "r"(dst), "l"(src) : "memory")

#define LDSM4(r0,r1,r2,r3,addr) \
    asm volatile("ldmatrix.sync.aligned.m8n8.x4.shared.b16 {%0,%1,%2,%3}, [%4];" \
                 : "=r"(r0),"=r"(r1),"=r"(r2),"=r"(r3) : "r"(addr))

#define MMA16816(c,a0,a1,a2,a3,b0,b1) \
    asm volatile("mma.sync.aligned.m16n8k16.row.col.f32.bf16.bf16.f32 " \
                 "{%0,%1,%2,%3},{%4,%5,%6,%7},{%8,%9},{%0,%1,%2,%3};" \
                 : "+f"(c[0]),"+f"(c[1]),"+f"(c[2]),"+f"(c[3]) \
                 : "r"(a0),"r"(a1),"r"(a2),"r"(a3),"r"(b0),"r"(b1))

// ---------------------------------------------------------------------------
// 1) L2 normalize + convert to packed bf16. One warp per row of 128 floats.
// ---------------------------------------------------------------------------
__global__ void knorm(const float* __restrict__ img, const float* __restrict__ text) {
    int wid  = blockIdx.x * 8 + (threadIdx.x >> 5);
    int lane = threadIdx.x & 31;
    const float* src; __nv_bfloat162* dst;
    if (wid < MROWS) { src = img + (size_t)wid * DD;  dst = g_imgh + (size_t)wid * (DD/2); }
    else { int r = wid - MROWS; src = text + (size_t)r * DD; dst = g_texth + (size_t)r * (DD/2); }
    float4 v = ((const float4*)src)[lane];
    float s = v.x*v.x + v.y*v.y + v.z*v.z + v.w*v.w;
    #pragma unroll
    for (int o = 16; o; o >>= 1) s += __shfl_xor_sync(0xffffffffu, s, o);
    float inv = 1.0f / fmaxf(sqrtf(s), 1e-12f);
    dst[lane*2]   = __floats2bfloat162_rn(v.x*inv, v.y*inv);
    dst[lane*2+1] = __floats2bfloat162_rn(v.z*inv, v.w*inv);
}

// ---------------------------------------------------------------------------
// 2) Persistent-strip HMMA GEMM + fused epilogue + fused final reduction.
//    CTA (nb, strip): B tile resident, 8 A-tiles double-buffered.
// ---------------------------------------------------------------------------
#define RPITCH 272
#define TILE_B (128 * RPITCH)            /* 34816 */
#define SM_BYTES (3 * TILE_B)            /* B + A0 + A1 = 104448 dynamic */

__global__ void __launch_bounds__(256) kgemm(float* __restrict__ out) {
    extern __shared__ char sh[];
    char* shB  = sh;
    char* shA[2] = { sh + TILE_B, sh + 2 * TILE_B };
    __shared__ float scol[8 * 128];
    __shared__ float sred[256];
    __shared__ unsigned slast;

    const int tid  = threadIdx.x;
    const int lane = tid & 31, w = tid >> 5;
    const int nb = blockIdx.x, strip = blockIdx.y;
    const int n0 = nb * 128;

    const uint32_t sBu = smem_u32(shB);
    const uint32_t sAu[2] = { smem_u32(shA[0]), smem_u32(shA[1]) };

    const int row = tid >> 1, q8 = (tid & 1) * 8;   // 2 threads per 256B row

    // ---- prologue: B tile + A tile 0 (group 0) ----------------------------
    {
        const uint4* gB = (const uint4*)(g_texth + (size_t)n0 * (DD/2));
        const uint4* gA = (const uint4*)(g_imgh  + (size_t)(strip * 8) * 128 * (DD/2));
        #pragma unroll
        for (int j = 0; j < 8; j++) {
            CPASYNC16(sBu    + row * RPITCH + (q8 + j) * 16, gB + row * 16 + q8 + j);
            CPASYNC16(sAu[0] + row * RPITCH + (q8 + j) * 16, gA + row * 16 + q8 + j);
        }
        asm volatile("cp.async.commit_group;" ::: "memory");
    }

    const uint32_t bBase = sBu + (uint32_t)((lane & 7) + ((lane >> 4) << 3)) * RPITCH
                               + (uint32_t)((lane >> 3) & 1) * 16;
    const uint32_t aOff  = (uint32_t)(w * 16 + (lane & 15)) * RPITCH
                               + (uint32_t)(lane >> 4) * 16;

    float colacc = 0.0f;

    for (int i = 0; i < 8; i++) {
        const int mt = strip * 8 + i;

        // prefetch next A tile (group i+1)
        if (i + 1 < 8) {
            const uint4* gA = (const uint4*)(g_imgh + (size_t)(mt + 1) * 128 * (DD/2));
            uint32_t dst = sAu[(i + 1) & 1];
            #pragma unroll
            for (int j = 0; j < 8; j++)
                CPASYNC16(dst + row * RPITCH + (q8 + j) * 16, gA + row * 16 + q8 + j);
            asm volatile("cp.async.commit_group;" ::: "memory");
            asm volatile("cp.async.wait_group 1;" ::: "memory");
        } else {
            asm volatile("cp.async.wait_group 0;" ::: "memory");
        }
        __syncthreads();

        // ---- mainloop on buffer i&1 --------------------------------------
        const uint32_t aBase = sAu[i & 1] + aOff;
        float c[16][4];
        #pragma unroll
        for (int t = 0; t < 16; t++)
            #pragma unroll
            for (int j = 0; j < 4; j++) c[t][j] = 0.0f;

        #pragma unroll
        for (int kk = 0; kk < 8; kk++) {
            uint32_t a0, a1, a2, a3;
            LDSM4(a0, a1, a2, a3, aBase + kk * 32);
            #pragma unroll
            for (int bt = 0; bt < 8; bt++) {
                uint32_t b0, b1, b2, b3;
                LDSM4(b0, b1, b2, b3, bBase + (uint32_t)bt * 8 * RPITCH + kk * 32);
                MMA16816(c[2*bt],   a0, a1, a2, a3, b0, b1);
                MMA16816(c[2*bt+1], a0, a1, a2, a3, b2, b3);
            }
        }

        // ---- epilogue: max over 16 rows of this warp's b-group -----------
        const int b = mt * 8 + w;
        float* scolw = scol + w * 128;
        float rowsum = 0.0f;

        #pragma unroll
        for (int t = 0; t < 16; t++) {
            float m0v = fmaxf(c[t][0], c[t][2]);
            float m1v = fmaxf(c[t][1], c[t][3]);
            #pragma unroll
            for (int o = 4; o <= 16; o <<= 1) {
                m0v = fmaxf(m0v, __shfl_xor_sync(0xffffffffu, m0v, o));
                m1v = fmaxf(m1v, __shfl_xor_sync(0xffffffffu, m1v, o));
            }
            if (lane < 4) {
                int colL = t * 8 + lane * 2;
                int col  = n0 + colL;
                if ((col >> 3) == b) {
                    g_diag[col]     = m0v;
                    g_diag[col + 1] = m1v;
                }
                float e0 = __expf(m0v), e1 = __expf(m1v);
                scolw[colL]     = e0;
                scolw[colL + 1] = e1;
                rowsum += e0 + e1;
            }
        }
        rowsum += __shfl_xor_sync(0xffffffffu, rowsum, 1);
        rowsum += __shfl_xor_sync(0xffffffffu, rowsum, 2);
        if (lane == 0) g_rowpart[nb * BB + b] = rowsum;

        __syncthreads();
        if (tid < 128) {
            float s = 0.0f;
            #pragma unroll
            for (int ww = 0; ww < 8; ww++) s += scol[ww * 128 + tid];
            colacc += s;
        }
        __syncthreads();     // protects scol and the A buffer being prefetched
    }

    if (tid < 128) g_colpart[strip * NCOLS + n0 + tid] = colacc;

    // ---- last-CTA fused final reduction -----------------------------------
    __threadfence();
    if (tid == 0) slast = atomicInc(&g_cnt, NCTA - 1);
    __syncthreads();
    if (slast != NCTA - 1) return;
    __threadfence();

    for (int col = tid; col < NCOLS; col += 256) {
        float s = 0.0f;
        #pragma unroll
        for (int j = 0; j < NSTRIP; j++) s += g_colpart[j * NCOLS + col];
        g_logden[col] = logf(s);
    }
    for (int b = tid; b < BB; b += 256) {
        float s = 0.0f;
        #pragma unroll
        for (int j = 0; j < NBLK; j++) s += g_rowpart[j * BB + b];
        g_logrow[b] = logf(s);
    }
    __syncthreads();

    float acc = 0.0f;
    for (int b = tid; b < BB; b += 256) {
        float d = 0.0f, l = 0.0f;
        #pragma unroll
        for (int t = 0; t < TT; t++) {
            d += g_diag[b * TT + t];
            l += g_logden[b * TT + t];
        }
        acc += 1.125f * d - g_logrow[b] - l;    // (1 + 1/T) = 1.125
    }
    sred[tid] = acc; __syncthreads();
    for (int o = 128; o; o >>= 1) {
        if (tid < o) sred[tid] += sred[tid + o];
        __syncthreads();
    }
    if (tid == 0) out[0] = -sred[0];
}

// ---------------------------------------------------------------------------
extern "C" void kernel_launch(void* const* d_in, const int* in_sizes, int n_in,
                              void* d_out, int out_size) {
    const float* img  = (const float*)d_in[0];
    const float* text = (const float*)d_in[1];
    if (n_in >= 2 && in_sizes[0] == NCOLS * DD && in_sizes[1] == MROWS * DD) {
        const float* t = img; img = text; text = t;
    }

    cudaFuncSetAttribute(kgemm, cudaFuncAttributeMaxDynamicSharedMemorySize, SM_BYTES);

    knorm<<<(MROWS + NCOLS) / 8, 256>>>(img, text);
    kgemm<<<dim3(NBLK, NSTRIP), 256, SM_BYTES>>>((float*)d_out);
}